// round 7
// baseline (speedup 1.0000x reference)
#include <cuda_runtime.h>

#define R_N 1000
#define C_N 81
#define NC  80          // foreground classes == grid size
#define NEGV (-1e9f)
#define SCORE_T 0.05f
#define IOU_T 0.5f
#define TOPK 100
#define GRID NC
#define BLOCK 512
#define CANDMAX 192
#define HBINS 8192      // 13-bit score histogram
#define HCHUNK (HBINS / BLOCK)   // 16 bins per thread

// ---------------- device scratch (no allocations allowed) ----------------
__device__ int g_cnt[NC];                          // per-class pre-NMS counts
__device__ unsigned long long g_clist[NC * R_N];   // per-class key lists
__device__ unsigned long long g_pool[NC * R_N];    // post-NMS survivor keys
__device__ float4 g_pbox[NC * R_N];                // survivor boxes by flat idx
__device__ int g_hist[HBINS];                      // global score histogram (post-NMS)
__device__ int g_count;
__device__ int g_c1;   // phase-A arrivals
__device__ int g_c2;   // phase-B ticket

// ---------------- helpers ----------------
__device__ __forceinline__ unsigned int ord32(float f) {
    unsigned int u = __float_as_uint(f);
    return (u & 0x80000000u) ? ~u : (u | 0x80000000u);
}
__device__ __forceinline__ float unord32(unsigned int u) {
    unsigned int b = (u & 0x80000000u) ? (u ^ 0x80000000u) : ~u;
    return __uint_as_float(b);
}
__device__ __forceinline__ float load_dim(const void* p) {
    int iv = *(const int*)p;
    if (iv > 0 && iv < 1000000) return (float)iv;   // passed as int
    return *(const float*)p;                         // passed as float
}
__device__ __forceinline__ void push_key(int c, int row, float prob) {
    // c in 1..80 (pre-NMS per-class list)
    if (prob > SCORE_T) {
        int slot = atomicAdd(&g_cnt[c - 1], 1);
        g_clist[(c - 1) * R_N + slot] =
            ((unsigned long long)ord32(prob) << 32) | (unsigned int)(~row);
    }
}
__device__ __forceinline__ void pool_push(unsigned long long key, unsigned int flat) {
    int p = atomicAdd(&g_count, 1);
    unsigned long long k = (key & 0xffffffff00000000ULL) | (unsigned int)(~flat);
    g_pool[p] = k;
    atomicAdd(&g_hist[(int)(k >> 51) & (HBINS - 1)], 1);
}

// decode + clip one box (class c in [1,80], row r) — exact reference math
__device__ __forceinline__ float4 decode_box(const float4* __restrict__ props4,
                                             const float4* __restrict__ reg4,
                                             int r, int c, float W, float H) {
    const float CLIPV = 4.135166556742356f;   // log(1000/16)
    float4 p = props4[r];
    float bw = p.z - p.x + 1.f, bh = p.w - p.y + 1.f;
    float cx = p.x + 0.5f * bw,  cy = p.y + 0.5f * bh;
    float4 rr = reg4[(size_t)r * C_N + c];
    float dx = rr.x / 10.0f;
    float dy = rr.y / 10.0f;
    float dw = fminf(rr.z / 5.0f, CLIPV);
    float dh = fminf(rr.w / 5.0f, CLIPV);
    float pcx = dx * bw + cx;
    float pcy = dy * bh + cy;
    float pw2 = expf(dw) * bw;
    float ph2 = expf(dh) * bh;
    float x1 = fminf(fmaxf(pcx - 0.5f * pw2, 0.f), W - 1.f);
    float y1 = fminf(fmaxf(pcy - 0.5f * ph2, 0.f), H - 1.f);
    float x2 = fminf(fmaxf(pcx + 0.5f * pw2 - 1.f, 0.f), W - 1.f);
    float y2 = fminf(fmaxf(pcy + 0.5f * ph2 - 1.f, 0.f), H - 1.f);
    return make_float4(x1, y1, x2, y2);
}

// descending bitonic sort over shared u64 array, n = power of two (fallback only)
__device__ void bitonic_desc(unsigned long long* a, int n) {
    for (unsigned int k = 2; k <= (unsigned int)n; k <<= 1) {
        for (unsigned int j = k >> 1; j > 0; j >>= 1) {
            for (unsigned int i = threadIdx.x; i < (unsigned int)n; i += BLOCK) {
                unsigned int l = i ^ j;
                if (l > i) {
                    unsigned long long x = a[i], y = a[l];
                    bool up = ((i & k) == 0);
                    if (up ? (x < y) : (x > y)) { a[i] = y; a[l] = x; }
                }
            }
            __syncthreads();
        }
    }
}

// ---------------- the single fused kernel ----------------
__global__ void __launch_bounds__(BLOCK) k_fused(
        const float* __restrict__ logits,
        const float* __restrict__ reg,
        const float* __restrict__ props,
        const void* pw, const void* ph,
        float* __restrict__ out) {

    __shared__ unsigned long long skey[1024];   // staged keys / fallback sort
    __shared__ unsigned long long sk2[1024];    // phase-C candidates
    __shared__ float sx1[1024], sy1[1024], sx2[1024], sy2[1024], sar[1024];
    __shared__ unsigned char srem[1024];
    __shared__ unsigned long long smask[64];
    __shared__ unsigned long long s_keep;
    __shared__ int shist[256];
    __shared__ int s_chunk[BLOCK];
    __shared__ int s_d, s_cum, s_bin, s_cnt, s_doC, s_thr, s_tot;

    int tid = threadIdx.x;
    int lane = tid & 31;
    const float4* props4 = (const float4*)props;
    const float4* reg4 = (const float4*)reg;
    float W = load_dim(pw), H = load_dim(ph);

    // ---------- Phase A: softmax stats + score filter + per-class push ----------
    {
        int row = blockIdx.x * (BLOCK / 32) + (tid >> 5);   // one warp per row
        if (row < R_N) {
            const float* lg = logits + (size_t)row * C_N;
            float a = (lane      < C_N) ? lg[lane]      : -INFINITY;
            float b = (lane + 32 < C_N) ? lg[lane + 32] : -INFINITY;
            float d = (lane + 64 < C_N) ? lg[lane + 64] : -INFINITY;
            float m = fmaxf(a, fmaxf(b, d));
            for (int o = 16; o; o >>= 1) m = fmaxf(m, __shfl_xor_sync(0xffffffffu, m, o));
            float ea = (lane      < C_N) ? expf(a - m) : 0.f;
            float eb = (lane + 32 < C_N) ? expf(b - m) : 0.f;
            float ed = (lane + 64 < C_N) ? expf(d - m) : 0.f;
            float s = ea + eb + ed;
            for (int o = 16; o; o >>= 1) s += __shfl_xor_sync(0xffffffffu, s, o);
            float inv = 1.f / s;
            if (lane >= 1)  push_key(lane,      row, ea * inv);   // c = 1..31
            push_key(lane + 32, row, eb * inv);                   // c = 32..63
            if (lane <= 16) push_key(lane + 64, row, ed * inv);   // c = 64..80
        }
    }
    __syncthreads();
    __threadfence();
    if (tid == 0) {
        atomicAdd(&g_c1, 1);
        while (*(volatile int*)&g_c1 < GRID) __nanosleep(32);   // all 80 blocks resident
    }
    __syncthreads();
    __threadfence();

    // ---------- Phase B: per-class NMS on pre-filtered list ----------
    int c0 = blockIdx.x;
    int c = c0 + 1;
    int M = *(volatile int*)&g_cnt[c0];

    if (M > 0 && M <= 64) {
        if (tid < M) skey[tid] = __ldcg(&g_clist[c0 * R_N + tid]);
        __syncthreads();
        unsigned long long mykey = 0ULL;
        float4 b;
        float A = 0.f;
        int rank = 0;
        if (tid < M) {
            mykey = skey[tid];
            for (int j = 0; j < M; j++) rank += (skey[j] > mykey);
            int r = (int)(~(unsigned int)mykey);
            b = decode_box(props4, reg4, r, c, W, H);
            A = (b.z - b.x + 1.f) * (b.w - b.y + 1.f);
            sx1[rank] = b.x; sy1[rank] = b.y; sx2[rank] = b.z; sy2[rank] = b.w;
            sar[rank] = A;
        }
        __syncthreads();
        if (tid < M) {
            unsigned long long msk = 0ULL;
            for (int j = rank + 1; j < M; j++) {
                float ix1 = fmaxf(b.x, sx1[j]), iy1 = fmaxf(b.y, sy1[j]);
                float ix2 = fminf(b.z, sx2[j]), iy2 = fminf(b.w, sy2[j]);
                float iw = fmaxf(ix2 - ix1 + 1.f, 0.f);
                float ih = fmaxf(iy2 - iy1 + 1.f, 0.f);
                float inter = iw * ih;
                float iou = inter / (A + sar[j] - inter);
                if (iou > IOU_T) msk |= (1ULL << j);
            }
            smask[rank] = msk;
        }
        __syncthreads();
        if (tid == 0) {
            unsigned long long removed = 0ULL, keep = 0ULL;
            for (int i = 0; i < M; i++)
                if (!((removed >> i) & 1ULL)) { keep |= (1ULL << i); removed |= smask[i]; }
            s_keep = keep;
        }
        __syncthreads();
        if (tid < M && ((s_keep >> rank) & 1ULL)) {
            unsigned int r = ~(unsigned int)mykey;
            pool_push(mykey, (unsigned int)(c0 * R_N) + r);
            g_pbox[(unsigned int)(c0 * R_N) + r] = b;
        }
    } else if (M > 64) {
        // fallback: sorted serial greedy (rare)
        for (int i = tid; i < M; i += BLOCK) skey[i] = __ldcg(&g_clist[c0 * R_N + i]);
        int n = 1; while (n < M) n <<= 1;
        for (int i = M + tid; i < n; i += BLOCK) skey[i] = 0ULL;
        __syncthreads();
        bitonic_desc(skey, n);
        for (int i = tid; i < M; i += BLOCK) {
            int r = (int)(~(unsigned int)skey[i]);
            float4 b = decode_box(props4, reg4, r, c, W, H);
            sx1[i] = b.x; sy1[i] = b.y; sx2[i] = b.z; sy2[i] = b.w;
            sar[i] = (b.z - b.x + 1.f) * (b.w - b.y + 1.f);
            srem[i] = 0;
        }
        __syncthreads();
        for (int i = 0; i < M; i++) {
            if (!srem[i]) {
                float X1 = sx1[i], Y1 = sy1[i], X2 = sx2[i], Y2 = sy2[i], A = sar[i];
                for (int j = i + 1 + tid; j < M; j += BLOCK) {
                    if (!srem[j]) {
                        float ix1 = fmaxf(X1, sx1[j]), iy1 = fmaxf(Y1, sy1[j]);
                        float ix2 = fminf(X2, sx2[j]), iy2 = fminf(Y2, sy2[j]);
                        float iw = fmaxf(ix2 - ix1 + 1.f, 0.f);
                        float ih = fmaxf(iy2 - iy1 + 1.f, 0.f);
                        float inter = iw * ih;
                        if (inter / (A + sar[j] - inter) > IOU_T) srem[j] = 1;
                    }
                }
            }
            __syncthreads();
        }
        for (int i = tid; i < M; i += BLOCK) {
            if (!srem[i]) {
                unsigned long long kk = skey[i];
                unsigned int r = ~(unsigned int)kk;
                pool_push(kk, (unsigned int)(c0 * R_N) + r);
                g_pbox[(unsigned int)(c0 * R_N) + r] =
                    make_float4(sx1[i], sy1[i], sx2[i], sy2[i]);
            }
        }
    }

    // ---------- ticket: last block to finish B runs phase C ----------
    __syncthreads();
    __threadfence();
    if (tid == 0) {
        int t = atomicAdd(&g_c2, 1);
        s_doC = (t == NC - 1);
    }
    __syncthreads();
    if (!s_doC) return;
    __threadfence();

    // ---------- Phase C: histogram threshold (precomputed) + rank placement ----------
    int K = atomicAdd(&g_count, 0);
    bool takeAll = (K <= 512);
    bool fastSel = false;
    int thr = 0;

    if (!takeAll) {
        // parallel suffix-scan of precomputed 8192-bin histogram
        int base = tid * HCHUNK;
        int cs = 0;
        int hloc[HCHUNK];
        #pragma unroll
        for (int b = 0; b < HCHUNK; b++) { hloc[b] = g_hist[base + b]; cs += hloc[b]; }
        s_chunk[tid] = cs;
        __syncthreads();
        int val = cs;
        for (int off = 1; off < BLOCK; off <<= 1) {
            int other = (tid + off < BLOCK) ? s_chunk[tid + off] : 0;
            __syncthreads();
            val += other;
            s_chunk[tid] = val;
            __syncthreads();
        }
        // val = inclusive suffix sum over chunks; find threshold bin inside my chunk
        int cum = val - cs;     // keys strictly above my chunk
        #pragma unroll
        for (int b = HCHUNK - 1; b >= 0; b--) {
            int h = hloc[b];
            if (cum < TOPK && cum + h >= TOPK) { s_thr = base + b; s_tot = cum + h; }
            cum += h;
        }
        __syncthreads();
        thr = s_thr;
        fastSel = (s_tot <= 512);
    }

    unsigned long long prefix = 0;
    int shift = 56;
    if (!takeAll && !fastSel) {
        // rare fallback: adaptive 64-bit radix descent
        int needed = TOPK;
        for (;;) {
            for (int i = tid; i < 256; i += BLOCK) shist[i] = 0;
            __syncthreads();
            for (int i = tid; i < K; i += BLOCK) {
                unsigned long long k = __ldcg(&g_pool[i]);
                bool act = (shift == 56) || ((k >> (shift + 8)) == prefix);
                if (act) atomicAdd(&shist[(int)((k >> shift) & 255)], 1);
            }
            __syncthreads();
            if (tid == 0) {
                int cum2 = 0, d;
                for (d = 255; d > 0; d--) {
                    int h = shist[d];
                    if (cum2 + h >= needed) break;
                    cum2 += h;
                }
                s_d = d; s_cum = cum2; s_bin = shist[d];
            }
            __syncthreads();
            needed -= s_cum;
            prefix = (prefix << 8) | (unsigned int)s_d;
            int binCount = s_bin;
            shift -= 8;
            if ((TOPK - needed) + binCount <= CANDMAX || shift < 0) break;
            __syncthreads();
        }
    }

    if (tid == 0) s_cnt = 0;
    __syncthreads();
    int sh = shift + 8;
    for (int i = tid; i < K; i += BLOCK) {
        unsigned long long k = __ldcg(&g_pool[i]);
        bool take = takeAll
                  ? true
                  : (fastSel ? (((int)(k >> 51) & (HBINS - 1)) >= thr)
                             : ((k >> sh) >= prefix));
        if (take) {
            int p = atomicAdd(&s_cnt, 1);
            if (p < 1024) sk2[p] = k;
        }
    }
    __syncthreads();
    int count = min(s_cnt, 1024);

    for (int i = tid; i < count; i += BLOCK) {
        unsigned long long kk = sk2[i];
        int rank = 0;
        for (int j = 0; j < count; j++) rank += (sk2[j] > kk);
        if (rank < TOPK) {
            unsigned int flat = ~(unsigned int)(kk & 0xffffffffu);
            float score = unord32((unsigned int)(kk >> 32));
            int cc = flat / R_N;
            float4 b = __ldcg(&g_pbox[flat]);
            out[rank] = score;
            out[TOPK + 4 * rank + 0] = b.x;
            out[TOPK + 4 * rank + 1] = b.y;
            out[TOPK + 4 * rank + 2] = b.z;
            out[TOPK + 4 * rank + 3] = b.w;
            out[5 * TOPK + rank] = (float)(cc + 1);
        }
    }
    if (count < TOPK && tid == 0) {
        // K < 100: fill remaining slots NEG-score, ascending unused flat idx
        int p = count;
        for (int f = 0; p < TOPK; f++) {
            bool used = false;
            for (int q = 0; q < count; q++) {
                unsigned int fl = ~(unsigned int)(sk2[q] & 0xffffffffu);
                if ((int)fl == f) { used = true; break; }
            }
            if (!used) {
                int cc = f / R_N;
                int r = f - cc * R_N;
                float4 b = decode_box(props4, reg4, r, cc + 1, W, H);
                out[p] = NEGV;
                out[TOPK + 4 * p + 0] = b.x;
                out[TOPK + 4 * p + 1] = b.y;
                out[TOPK + 4 * p + 2] = b.z;
                out[TOPK + 4 * p + 3] = b.w;
                out[5 * TOPK + p] = (float)(cc + 1);
                p++;
            }
        }
    }

    // reset scratch for next graph replay (only this block is alive)
    for (int i = tid; i < HBINS; i += BLOCK) g_hist[i] = 0;
    if (tid < NC) g_cnt[tid] = 0;
    if (tid == 0) { g_c1 = 0; g_c2 = 0; g_count = 0; }
    __threadfence();
}

// ---------------- launch ----------------
extern "C" void kernel_launch(void* const* d_in, const int* in_sizes, int n_in,
                              void* d_out, int out_size) {
    const float *logits = nullptr, *reg = nullptr, *props = nullptr;
    const void *pw = nullptr, *ph = nullptr;
    for (int i = 0; i < n_in; i++) {
        int s = in_sizes[i];
        if (s == R_N * C_N)            logits = (const float*)d_in[i];
        else if (s == R_N * C_N * 4)   reg    = (const float*)d_in[i];
        else if (s == R_N * 4)         props  = (const float*)d_in[i];
        else if (s == 1) { if (!pw) pw = d_in[i]; else ph = d_in[i]; }
    }
    k_fused<<<GRID, BLOCK>>>(logits, reg, props, pw, ph, (float*)d_out);
}